// round 12
// baseline (speedup 1.0000x reference)
#include <cuda_runtime.h>
#include <cstdint>
#include <math_constants.h>

// RealNVP, exact piecewise-linear collapse. R12 over R11 (309.5us = 254.7 flow
// + ~55 prep):
//  (1) flow state (z1,z2,ld) register-resident: each thread owns 4 quads for
//      all 15 layers (was smem: 6 x 16B smem ops per quad-layer).
//  (2) grid cells carry a PURE flag (bit15): pure cell => segment known, no
//      verification walk load (~92% of evals).
//  (3) prep at 512 threads (sort iters halved), prep ~55 -> ~25us.

#define NLAYERS 15
#define MAXK    1280          // merged knees bound: 2*560=1120
#define KSORT   2048
#define GCELLS  2048
#define PREP_T  512
#define MAIN_T  512
#define NQ      4

__device__ float  g_B [NLAYERS][MAXK];      // knots; B[0]=-inf, +inf padded
__device__ float4 g_AV[NLAYERS][MAXK];      // (A, Vs, Ss, Vt)
__device__ float  g_St[NLAYERS][MAXK];      // St
__device__ unsigned short g_grid[NLAYERS][GCELLS];  // bit15=impure, low15=idx
__device__ float  g_x0[NLAYERS], g_invh[NLAYERS];

__device__ __forceinline__ float fast_tanh(float x) {
    float e = __expf(2.0f * x);
    float r = __frcp_rn(e + 1.0f);
    return fmaf(-2.0f, r, 1.0f);
}

// ---------------------------------------------------------------------------
// Prep: one block per LAYER; builds the merged table + pure-flagged grid.
// ---------------------------------------------------------------------------
__global__ void prep_kernel(
    const float* __restrict__ sW1, const float* __restrict__ sb1,
    const float* __restrict__ sW2, const float* __restrict__ sb2,
    const float* __restrict__ sW3, const float* __restrict__ sb3,
    const float* __restrict__ tW1, const float* __restrict__ tb1,
    const float* __restrict__ tW2, const float* __restrict__ tb2,
    const float* __restrict__ tW3, const float* __restrict__ tb3)
{
    __shared__ float w1[2][32], b1[2][32], W2s[2][512], b2s[2][16], w3s[2][16], b3s[2];
    __shared__ float K[KSORT];
    __shared__ float X[34];
    __shared__ int cnt, m1s;

    int tid = threadIdx.x;
    int l = blockIdx.x;

    for (int i = tid; i < 32; i += PREP_T) {
        w1[0][i] = sW1[l*32+i]; b1[0][i] = sb1[l*32+i];
        w1[1][i] = tW1[l*32+i]; b1[1][i] = tb1[l*32+i];
    }
    for (int i = tid; i < 512; i += PREP_T) {
        W2s[0][i] = sW2[l*512+i]; W2s[1][i] = tW2[l*512+i];
    }
    for (int i = tid; i < 16; i += PREP_T) {
        b2s[0][i] = sb2[l*16+i]; w3s[0][i] = sW3[l*16+i];
        b2s[1][i] = tb2[l*16+i]; w3s[1][i] = tW3[l*16+i];
    }
    if (tid == 0) { b3s[0] = sb3[l]; b3s[1] = tb3[l]; cnt = 0; }
    for (int i = tid; i < KSORT; i += PREP_T) K[i] = CUDART_INF_F;
    __syncthreads();

    // knees for each MLP
    for (int p = 0; p < 2; p++) {
        if (tid == 0) {
            int m1 = 0;
            for (int i = 0; i < 32; i++)
                if (w1[p][i] != 0.0f) X[++m1] = -b1[p][i] / w1[p][i];
            for (int a = 2; a <= m1; a++) {          // insertion sort X[1..m1]
                float v = X[a]; int b = a - 1;
                while (b >= 1 && X[b] > v) { X[b + 1] = X[b]; b--; }
                X[b + 1] = v;
            }
            X[0] = -CUDART_INF_F; X[m1 + 1] = CUDART_INF_F;
            m1s = m1;
            int c0 = cnt;
            for (int a = 1; a <= m1; a++) K[c0 + a - 1] = X[a];  // L1 knees
            cnt = c0 + m1;
        }
        __syncthreads();
        int m1 = m1s;
        int ntask = (m1 + 1) * 16;
        for (int t = tid; t < ntask; t += PREP_T) {
            int iv = t >> 4, j = t & 15;
            float lo = X[iv], hi = X[iv + 1];
            float xm;
            if (!isfinite(lo) && !isfinite(hi)) xm = 0.0f;
            else if (!isfinite(lo)) xm = hi - 1.0f;
            else if (!isfinite(hi)) xm = lo + 1.0f;
            else xm = 0.5f * (lo + hi);
            float c = b2s[p][j], d = 0.0f;
            for (int i = 0; i < 32; i++) {
                float pre = fmaf(w1[p][i], xm, b1[p][i]);
                float s1 = (pre >= 0.0f) ? 1.0f : 0.01f;
                float wij = W2s[p][i * 16 + j];
                d = fmaf(wij * s1, w1[p][i], d);
                c = fmaf(wij * s1, b1[p][i], c);
            }
            if (d != 0.0f) {
                float r = -c / d;
                if (isfinite(r) && r > lo && r < hi) {
                    int pos = atomicAdd(&cnt, 1);
                    K[pos] = r;
                }
            }
        }
        __syncthreads();
    }
    int m = cnt;

    // bitonic sort K[0..KSORT)
    for (int k = 2; k <= KSORT; k <<= 1) {
        for (int j = k >> 1; j > 0; j >>= 1) {
            __syncthreads();
            for (int t = tid; t < KSORT / 2; t += PREP_T) {
                int i = ((t / j) * (j << 1)) + (t & (j - 1));
                int q = i + j;
                float a = K[i], b = K[q];
                bool up = ((i & k) == 0);
                if (up ? (a > b) : (a < b)) { K[i] = b; K[q] = a; }
            }
        }
    }
    __syncthreads();

    // write B: B[0]=-inf, B[1..m]=K[0..m-1], rest +inf
    for (int kk = tid; kk < MAXK; kk += PREP_T) {
        float v = (kk == 0) ? -CUDART_INF_F : (kk <= m ? K[kk - 1] : CUDART_INF_F);
        g_B[l][kk] = v;
    }
    __syncthreads();

    // per-segment payload (A, Vs, Ss, Vt, St); segment idx covers [B[idx],B[idx+1])
    for (int idx = tid; idx <= m; idx += PREP_T) {
        float Bl = (idx == 0) ? -CUDART_INF_F : K[idx - 1];
        float Br = (idx < m) ? K[idx] : CUDART_INF_F;
        float A  = isfinite(Bl) ? Bl : ((m >= 1) ? K[0] : 0.0f);
        float xm;
        if (!isfinite(Bl) && !isfinite(Br)) xm = 0.0f;
        else if (!isfinite(Bl)) xm = Br - 1.0f;
        else if (!isfinite(Br)) xm = Bl + 1.0f;
        else { xm = 0.5f * (Bl + Br); if (!(xm > Bl && xm < Br)) xm = Bl; }

        float V[2], S[2];
        for (int p = 0; p < 2; p++) {
            float acc[16];
#pragma unroll
            for (int j = 0; j < 16; j++) acc[j] = b2s[p][j];
            for (int i = 0; i < 32; i++) {
                float pre = fmaf(w1[p][i], A, b1[p][i]);
                float h = fmaxf(pre, 0.01f * pre);
#pragma unroll
                for (int j = 0; j < 16; j++) acc[j] = fmaf(h, W2s[p][i * 16 + j], acc[j]);
            }
            float Vv = b3s[p];
#pragma unroll
            for (int j = 0; j < 16; j++) {
                float hh = fmaxf(acc[j], 0.01f * acc[j]);
                Vv = fmaf(hh, w3s[p][j], Vv);
            }
            float a2[16], dd[16];
#pragma unroll
            for (int j = 0; j < 16; j++) { a2[j] = b2s[p][j]; dd[j] = 0.0f; }
            for (int i = 0; i < 32; i++) {
                float pre = fmaf(w1[p][i], xm, b1[p][i]);
                float s1 = (pre >= 0.0f) ? 1.0f : 0.01f;
                float h = s1 * pre;
                float dh = s1 * w1[p][i];
#pragma unroll
                for (int j = 0; j < 16; j++) {
                    float wij = W2s[p][i * 16 + j];
                    a2[j] = fmaf(h, wij, a2[j]);
                    dd[j] = fmaf(dh, wij, dd[j]);
                }
            }
            float Sv = 0.0f;
#pragma unroll
            for (int j = 0; j < 16; j++) {
                float s2 = (a2[j] >= 0.0f) ? 1.0f : 0.01f;
                Sv = fmaf(w3s[p][j] * s2, dd[j], Sv);
            }
            V[p] = Vv; S[p] = Sv;
        }
        g_AV[l][idx] = make_float4(A, V[0], S[0], V[1]);
        g_St[l][idx] = S[1];
    }
    for (int idx = m + 1 + tid; idx < MAXK; idx += PREP_T) {
        g_AV[l][idx] = make_float4(0.f, 0.f, 0.f, 0.f);
        g_St[l][idx] = 0.f;
    }
    __syncthreads();

    // uniform grid with pure-cell flag
    float x0 = (m >= 1) ? K[0] : 0.0f;
    float xr = (m >= 1) ? K[m - 1] : 0.0f;
    float invh = (m >= 2 && xr > x0) ? (float)GCELLS / (xr - x0) : 0.0f;
    float h = (invh > 0.0f) ? (xr - x0) / (float)GCELLS : 0.0f;
    if (tid == 0) { g_x0[l] = x0; g_invh[l] = invh; }
    float wd = 0.01f * h;                    // widen: 1% of a cell (>> ulp noise)
    for (int g = tid; g < GCELLS; g += PREP_T) {
        int ilo = 0, ihi = 0;
        if (m >= 1) {
            float xlo = x0 + (float)g * h - wd;
            float xhi = x0 + (float)(g + 1) * h + wd;
            // locate(x) = largest idx in [0,m] with B[idx] <= x  (B[i]=K[i-1])
            int lo = 0, hi = m;
            while (lo < hi) { int mid = (lo + hi + 1) >> 1; if (K[mid-1] <= xlo) lo = mid; else hi = mid - 1; }
            ilo = lo;
            lo = 0; hi = m;
            while (lo < hi) { int mid = (lo + hi + 1) >> 1; if (K[mid-1] <= xhi) lo = mid; else hi = mid - 1; }
            ihi = lo;
        }
        bool impure = (ilo != ihi) || (g == 0) || (g == GCELLS - 1);
        g_grid[l][g] = (unsigned short)(ilo | (impure ? 0x8000 : 0));
    }
}

// ---------------------------------------------------------------------------
// Flow kernel: register-resident state, 4 quads/thread, strided ownership.
// ---------------------------------------------------------------------------
extern __shared__ float4 smb[];

__global__ __launch_bounds__(MAIN_T, 1) void flow_kernel(
    const float* __restrict__ x,
    const float* __restrict__ scale_w, const float* __restrict__ scale_b,
    float* __restrict__ out, int nquads)
{
    float4* AVs = smb;                             // MAXK float4
    float*  Bs  = (float*)(AVs + MAXK);            // MAXK
    float*  Sts = Bs + MAXK;                       // MAXK
    unsigned short* Gs = (unsigned short*)(Sts + MAXK);  // GCELLS

    int tid = threadIdx.x;
    int gtid = blockIdx.x * MAIN_T + tid;
    int NT = gridDim.x * MAIN_T;

    float4 Rz1[NQ], Rz2[NQ], Rld[NQ];
    const float4* x4 = (const float4*)x;
#pragma unroll
    for (int k = 0; k < NQ; k++) {
        int Q = gtid + k * NT;
        if (Q < nquads) {
            float4 a = x4[2 * Q], b = x4[2 * Q + 1];
            Rz1[k] = make_float4(a.y, a.w, b.y, b.w);   // x[:,1]
            Rz2[k] = make_float4(a.x, a.z, b.x, b.z);   // x[:,0]
        } else {
            Rz1[k] = make_float4(0.f, 0.f, 0.f, 0.f);
            Rz2[k] = make_float4(0.f, 0.f, 0.f, 0.f);
        }
        Rld[k] = make_float4(0.f, 0.f, 0.f, 0.f);
    }

    for (int l = 0; l < NLAYERS; l++) {
        __syncthreads();
        {
            const float*  gB = g_B[l];
            const float4* gA = g_AV[l];
            const float*  gS = g_St[l];
            const unsigned short* gG = g_grid[l];
            for (int kk2 = tid; kk2 < MAXK; kk2 += MAIN_T) {
                Bs[kk2] = gB[kk2]; AVs[kk2] = gA[kk2]; Sts[kk2] = gS[kk2];
            }
            for (int g = tid; g < GCELLS; g += MAIN_T) Gs[g] = gG[g];
        }
        float x0 = g_x0[l], invh = g_invh[l];
        float sw = scale_w[l], sb = scale_b[l];
        __syncthreads();

#pragma unroll
        for (int k = 0; k < NQ; k++) {
            int Q = gtid + k * NT;
            if (Q >= nquads) continue;             // warp-uniform (strided)
            float4 z1 = Rz1[k], z2 = Rz2[k], ld = Rld[k];
            float x1v[4] = {z2.x, z2.y, z2.z, z2.w};
            float x2v[4] = {z1.x, z1.y, z1.z, z1.w};
            float zn[4], lg[4];
#pragma unroll
            for (int e = 0; e < 4; e++) {
                float xv = x1v[e];
                int c = (int)((xv - x0) * invh);
                c = min(max(c, 0), GCELLS - 1);
                unsigned int e16 = Gs[c];
                int idx = e16 & 0x7FFF;
                if (e16 & 0x8000u) {
                    while (Bs[idx + 1] <= xv) idx++;
                }
                float4 av = AVs[idx];
                float st = Sts[idx];
                float dx = xv - av.x;
                float sv = fmaf(av.z, dx, av.y);
                float tv = fmaf(st,   dx, av.w);
                float logs = fmaf(fast_tanh(sv), sw, sb);
                zn[e] = fmaf(__expf(logs), x2v[e], tv);
                lg[e] = logs;
            }
            Rz1[k] = z2;
            Rz2[k] = make_float4(zn[0], zn[1], zn[2], zn[3]);
            Rld[k] = make_float4(ld.x + lg[0], ld.y + lg[1],
                                 ld.z + lg[2], ld.w + lg[3]);
        }
    }

    float4* o4  = (float4*)out;
    float4* ld4 = (float4*)(out + 8 * (size_t)nquads);
#pragma unroll
    for (int k = 0; k < NQ; k++) {
        int Q = gtid + k * NT;
        if (Q >= nquads) continue;
        float4 z1 = Rz1[k], z2 = Rz2[k];
        o4[2 * Q]     = make_float4(z1.x, z2.x, z1.y, z2.y);
        o4[2 * Q + 1] = make_float4(z1.z, z2.z, z1.w, z2.w);
        ld4[Q] = Rld[k];
    }
}

extern "C" void kernel_launch(void* const* d_in, const int* in_sizes, int n_in,
                              void* d_out, int out_size) {
    const float* x       = (const float*)d_in[0];
    const float* scale_w = (const float*)d_in[1];
    const float* scale_b = (const float*)d_in[2];
    const float* sW1 = (const float*)d_in[3];
    const float* sb1 = (const float*)d_in[4];
    const float* sW2 = (const float*)d_in[5];
    const float* sb2 = (const float*)d_in[6];
    const float* sW3 = (const float*)d_in[7];
    const float* sb3 = (const float*)d_in[8];
    const float* tW1 = (const float*)d_in[9];
    const float* tb1 = (const float*)d_in[10];
    const float* tW2 = (const float*)d_in[11];
    const float* tb2 = (const float*)d_in[12];
    const float* tW3 = (const float*)d_in[13];
    const float* tb3 = (const float*)d_in[14];
    float* out = (float*)d_out;

    int nquads = in_sizes[0] / 8;
    int grid = (nquads + MAIN_T * NQ - 1) / (MAIN_T * NQ);
    if (grid < 296) grid = 296;            // 2 even waves on 148 SMs

    const int smem_main = MAXK * 16 + 2 * MAXK * 4 + GCELLS * 2;  // 34,816 B
    cudaFuncSetAttribute(flow_kernel, cudaFuncAttributeMaxDynamicSharedMemorySize, smem_main);

    prep_kernel<<<NLAYERS, PREP_T>>>(sW1, sb1, sW2, sb2, sW3, sb3,
                                     tW1, tb1, tW2, tb2, tW3, tb3);
    flow_kernel<<<grid, MAIN_T, smem_main>>>(x, scale_w, scale_b, out, nquads);
}

// round 14
// speedup vs baseline: 1.4883x; 1.4883x over previous
#include <cuda_runtime.h>
#include <cstdint>
#include <math_constants.h>

// RealNVP, exact piecewise-linear collapse.
// R14 = R13 with the crash fixed:
//  - __launch_bounds__ on ALL kernels (R13's prep_a @1024thr without bounds
//    could exceed the RF -> failed launch -> zeroed tables -> runaway walk).
//  - prep_a back to 512 threads (R12-validated), keeps dynamic-width sort.
//  - flow walk clamped by m (no OOB even if tables are corrupt).
// Flow = R11 structure (smem state, 1024 thr, 296 CTAs) + pure-cell flag.

#define NLAYERS 15
#define MAXK    1280          // merged knees bound: 2*560=1120
#define KSORT   2048
#define GCELLS  2048
#define PREPA_T 512
#define PREPB_T 256
#define SPLIT   8             // prep_b blocks per layer
#define MAIN_T  1024
#define QPC     3543          // quads per CTA; 296 CTAs for N=4194304

__device__ float  g_B [NLAYERS][MAXK];      // knots; B[0]=-inf, +inf padded
__device__ float4 g_AV[NLAYERS][MAXK];      // (A, Vs, Ss, Vt)
__device__ float  g_St[NLAYERS][MAXK];      // St
__device__ unsigned short g_grid[NLAYERS][GCELLS];  // bit15=impure, low15=idx
__device__ float  g_x0[NLAYERS], g_invh[NLAYERS], g_h[NLAYERS];
__device__ int    g_m[NLAYERS];

__device__ __forceinline__ float fast_tanh(float x) {
    float e = __expf(2.0f * x);
    float r = __frcp_rn(e + 1.0f);
    return fmaf(-2.0f, r, 1.0f);
}

// ---------------------------------------------------------------------------
// prep_a: one block per layer. Knees -> dynamic-width bitonic sort -> B, m.
// ---------------------------------------------------------------------------
__global__ __launch_bounds__(PREPA_T, 1) void prep_a_kernel(
    const float* __restrict__ sW1, const float* __restrict__ sb1,
    const float* __restrict__ sW2, const float* __restrict__ sb2,
    const float* __restrict__ tW1, const float* __restrict__ tb1,
    const float* __restrict__ tW2, const float* __restrict__ tb2)
{
    __shared__ float w1[2][32], b1[2][32], W2s[2][512], b2s[2][16];
    __shared__ float K[KSORT];
    __shared__ float X[34];
    __shared__ int cnt, m1s;

    int tid = threadIdx.x;
    int l = blockIdx.x;

    for (int i = tid; i < 32; i += PREPA_T) {
        w1[0][i] = sW1[l*32+i]; b1[0][i] = sb1[l*32+i];
        w1[1][i] = tW1[l*32+i]; b1[1][i] = tb1[l*32+i];
    }
    for (int i = tid; i < 512; i += PREPA_T) {
        W2s[0][i] = sW2[l*512+i]; W2s[1][i] = tW2[l*512+i];
    }
    for (int i = tid; i < 16; i += PREPA_T) {
        b2s[0][i] = sb2[l*16+i]; b2s[1][i] = tb2[l*16+i];
    }
    if (tid == 0) cnt = 0;
    for (int i = tid; i < KSORT; i += PREPA_T) K[i] = CUDART_INF_F;
    __syncthreads();

    for (int p = 0; p < 2; p++) {
        if (tid == 0) {
            int m1 = 0;
            for (int i = 0; i < 32; i++)
                if (w1[p][i] != 0.0f) X[++m1] = -b1[p][i] / w1[p][i];
            for (int a = 2; a <= m1; a++) {          // insertion sort X[1..m1]
                float v = X[a]; int b = a - 1;
                while (b >= 1 && X[b] > v) { X[b + 1] = X[b]; b--; }
                X[b + 1] = v;
            }
            X[0] = -CUDART_INF_F; X[m1 + 1] = CUDART_INF_F;
            m1s = m1;
            int c0 = cnt;
            for (int a = 1; a <= m1; a++) K[c0 + a - 1] = X[a];
            cnt = c0 + m1;
        }
        __syncthreads();
        int m1 = m1s;
        int ntask = (m1 + 1) * 16;
        for (int t = tid; t < ntask; t += PREPA_T) {
            int iv = t >> 4, j = t & 15;
            float lo = X[iv], hi = X[iv + 1];
            float xm;
            if (!isfinite(lo) && !isfinite(hi)) xm = 0.0f;
            else if (!isfinite(lo)) xm = hi - 1.0f;
            else if (!isfinite(hi)) xm = lo + 1.0f;
            else xm = 0.5f * (lo + hi);
            float c = b2s[p][j], d = 0.0f;
            for (int i = 0; i < 32; i++) {
                float pre = fmaf(w1[p][i], xm, b1[p][i]);
                float s1 = (pre >= 0.0f) ? 1.0f : 0.01f;
                float wij = W2s[p][i * 16 + j];
                d = fmaf(wij * s1, w1[p][i], d);
                c = fmaf(wij * s1, b1[p][i], c);
            }
            if (d != 0.0f) {
                float r = -c / d;
                if (isfinite(r) && r > lo && r < hi) {
                    int pos = atomicAdd(&cnt, 1);
                    K[pos] = r;
                }
            }
        }
        __syncthreads();
    }
    int m = cnt;
    if (m > MAXK - 2) m = MAXK - 2;        // paranoia clamp (bound is 1120)

    // dynamic-width bitonic sort: width Ks = next_pow2(m) (rest are +inf)
    int Ks = 2;
    while (Ks < m) Ks <<= 1;
    for (int k = 2; k <= Ks; k <<= 1) {
        for (int j = k >> 1; j > 0; j >>= 1) {
            __syncthreads();
            for (int t = tid; t < (Ks >> 1); t += PREPA_T) {
                int i = ((t / j) * (j << 1)) + (t & (j - 1));
                int q = i + j;
                float a = K[i], b = K[q];
                bool up = ((i & k) == 0);
                if (up ? (a > b) : (a < b)) { K[i] = b; K[q] = a; }
            }
        }
    }
    __syncthreads();

    for (int kk = tid; kk < MAXK; kk += PREPA_T) {
        float v = (kk == 0) ? -CUDART_INF_F : (kk <= m ? K[kk - 1] : CUDART_INF_F);
        g_B[l][kk] = v;
    }
    if (tid == 0) {
        g_m[l] = m;
        float x0 = (m >= 1) ? K[0] : 0.0f;
        float xr = (m >= 1) ? K[m - 1] : 0.0f;
        float invh = (m >= 2 && xr > x0) ? (float)GCELLS / (xr - x0) : 0.0f;
        g_x0[l] = x0;
        g_invh[l] = invh;
        g_h[l] = (invh > 0.0f) ? (xr - x0) / (float)GCELLS : 0.0f;
    }
}

// ---------------------------------------------------------------------------
// prep_b: SPLIT blocks per layer. Per-segment payloads + grid cells.
// ---------------------------------------------------------------------------
__global__ __launch_bounds__(PREPB_T, 1) void prep_b_kernel(
    const float* __restrict__ sW1, const float* __restrict__ sb1,
    const float* __restrict__ sW2, const float* __restrict__ sb2,
    const float* __restrict__ sW3, const float* __restrict__ sb3,
    const float* __restrict__ tW1, const float* __restrict__ tb1,
    const float* __restrict__ tW2, const float* __restrict__ tb2,
    const float* __restrict__ tW3, const float* __restrict__ tb3)
{
    __shared__ float w1[2][32], b1[2][32], W2s[2][512], b2s[2][16], w3s[2][16], b3s[2];

    int tid = threadIdx.x;
    int l = blockIdx.x / SPLIT;
    int s = blockIdx.x % SPLIT;

    for (int i = tid; i < 32; i += PREPB_T) {
        w1[0][i] = sW1[l*32+i]; b1[0][i] = sb1[l*32+i];
        w1[1][i] = tW1[l*32+i]; b1[1][i] = tb1[l*32+i];
    }
    for (int i = tid; i < 512; i += PREPB_T) {
        W2s[0][i] = sW2[l*512+i]; W2s[1][i] = tW2[l*512+i];
    }
    for (int i = tid; i < 16; i += PREPB_T) {
        b2s[0][i] = sb2[l*16+i]; w3s[0][i] = sW3[l*16+i];
        b2s[1][i] = tb2[l*16+i]; w3s[1][i] = tW3[l*16+i];
    }
    if (tid == 0) { b3s[0] = sb3[l]; b3s[1] = tb3[l]; }
    __syncthreads();

    int m = g_m[l];
    const float* B = g_B[l];

    const int CH = MAXK / SPLIT;                  // 160
    for (int idx = s * CH + tid; idx < (s + 1) * CH; idx += PREPB_T) {
        if (idx > m) {
            g_AV[l][idx] = make_float4(0.f, 0.f, 0.f, 0.f);
            g_St[l][idx] = 0.f;
            continue;
        }
        float Bl = B[idx];
        float Br = B[idx + 1];
        float A  = isfinite(Bl) ? Bl : ((m >= 1) ? B[1] : 0.0f);
        float xm;
        if (!isfinite(Bl) && !isfinite(Br)) xm = 0.0f;
        else if (!isfinite(Bl)) xm = Br - 1.0f;
        else if (!isfinite(Br)) xm = Bl + 1.0f;
        else { xm = 0.5f * (Bl + Br); if (!(xm > Bl && xm < Br)) xm = Bl; }

        float V[2], S[2];
        for (int p = 0; p < 2; p++) {
            float acc[16];
#pragma unroll
            for (int j = 0; j < 16; j++) acc[j] = b2s[p][j];
            for (int i = 0; i < 32; i++) {
                float pre = fmaf(w1[p][i], A, b1[p][i]);
                float h = fmaxf(pre, 0.01f * pre);
#pragma unroll
                for (int j = 0; j < 16; j++) acc[j] = fmaf(h, W2s[p][i * 16 + j], acc[j]);
            }
            float Vv = b3s[p];
#pragma unroll
            for (int j = 0; j < 16; j++) {
                float hh = fmaxf(acc[j], 0.01f * acc[j]);
                Vv = fmaf(hh, w3s[p][j], Vv);
            }
            float a2[16], dd[16];
#pragma unroll
            for (int j = 0; j < 16; j++) { a2[j] = b2s[p][j]; dd[j] = 0.0f; }
            for (int i = 0; i < 32; i++) {
                float pre = fmaf(w1[p][i], xm, b1[p][i]);
                float s1 = (pre >= 0.0f) ? 1.0f : 0.01f;
                float h = s1 * pre;
                float dh = s1 * w1[p][i];
#pragma unroll
                for (int j = 0; j < 16; j++) {
                    float wij = W2s[p][i * 16 + j];
                    a2[j] = fmaf(h, wij, a2[j]);
                    dd[j] = fmaf(dh, wij, dd[j]);
                }
            }
            float Sv = 0.0f;
#pragma unroll
            for (int j = 0; j < 16; j++) {
                float s2 = (a2[j] >= 0.0f) ? 1.0f : 0.01f;
                Sv = fmaf(w3s[p][j] * s2, dd[j], Sv);
            }
            V[p] = Vv; S[p] = Sv;
        }
        g_AV[l][idx] = make_float4(A, V[0], S[0], V[1]);
        g_St[l][idx] = S[1];
    }

    const int GC = GCELLS / SPLIT;                // 256
    float x0 = g_x0[l], h = g_h[l];
    float wd = 0.01f * h;
    for (int g = s * GC + tid; g < (s + 1) * GC; g += PREPB_T) {
        int ilo = 0, ihi = 0;
        if (m >= 1) {
            float xlo = x0 + (float)g * h - wd;
            float xhi = x0 + (float)(g + 1) * h + wd;
            int lo = 0, hi = m;
            while (lo < hi) { int mid = (lo + hi + 1) >> 1; if (B[mid] <= xlo) lo = mid; else hi = mid - 1; }
            ilo = lo;
            lo = 0; hi = m;
            while (lo < hi) { int mid = (lo + hi + 1) >> 1; if (B[mid] <= xhi) lo = mid; else hi = mid - 1; }
            ihi = lo;
        }
        bool impure = (ilo != ihi) || (g == 0) || (g == GCELLS - 1);
        g_grid[l][g] = (unsigned short)(ilo | (impure ? 0x8000 : 0));
    }
}

// ---------------------------------------------------------------------------
// Flow kernel: R11 structure (smem state) + pure-cell fast path + clamped walk.
// ---------------------------------------------------------------------------
extern __shared__ float4 smb[];

__global__ __launch_bounds__(MAIN_T, 1) void flow_kernel(
    const float* __restrict__ x,
    const float* __restrict__ scale_w, const float* __restrict__ scale_b,
    float* __restrict__ out, int nquads)
{
    float4* AVs = smb;                     // MAXK float4
    float4* SZ1 = AVs + MAXK;              // QPC
    float4* SZ2 = SZ1 + QPC;
    float4* SLD = SZ2 + QPC;
    float*  Bs  = (float*)(SLD + QPC);     // MAXK
    float*  Sts = Bs + MAXK;               // MAXK
    unsigned short* Gs = (unsigned short*)(Sts + MAXK);  // GCELLS

    int tid = threadIdx.x;
    int q0 = blockIdx.x * QPC;
    int nq = nquads - q0;
    if (nq > QPC) nq = QPC;

    const float4* x4 = (const float4*)x;
    for (int lq = tid; lq < nq; lq += MAIN_T) {
        int Q = q0 + lq;
        float4 a = x4[2 * Q], b = x4[2 * Q + 1];
        SZ1[lq] = make_float4(a.y, a.w, b.y, b.w);   // x[:,1]
        SZ2[lq] = make_float4(a.x, a.z, b.x, b.z);   // x[:,0]
        SLD[lq] = make_float4(0.f, 0.f, 0.f, 0.f);
    }

    for (int l = 0; l < NLAYERS; l++) {
        __syncthreads();
        {
            const float*  gB = g_B[l];
            const float4* gA = g_AV[l];
            const float*  gS = g_St[l];
            const unsigned short* gG = g_grid[l];
            for (int k = tid; k < MAXK; k += MAIN_T) {
                Bs[k] = gB[k]; AVs[k] = gA[k]; Sts[k] = gS[k];
            }
            for (int g = tid; g < GCELLS; g += MAIN_T) Gs[g] = gG[g];
        }
        int mloc = g_m[l];
        float x0 = g_x0[l], invh = g_invh[l];
        float sw = scale_w[l], sb = scale_b[l];
        __syncthreads();

        for (int lq = tid; lq < nq; lq += MAIN_T) {
            float4 z1 = SZ1[lq], z2 = SZ2[lq], ld = SLD[lq];
            float x1v[4] = {z2.x, z2.y, z2.z, z2.w};
            float x2v[4] = {z1.x, z1.y, z1.z, z1.w};
            float zn[4], lg[4];
#pragma unroll
            for (int e = 0; e < 4; e++) {
                float xv = x1v[e];
                int c = (int)((xv - x0) * invh);
                c = min(max(c, 0), GCELLS - 1);
                unsigned int e16 = Gs[c];
                int idx = e16 & 0x7FFF;
                if (e16 & 0x8000u) {
                    while (idx < mloc && Bs[idx + 1] <= xv) idx++;
                }
                float4 av = AVs[idx];
                float st = Sts[idx];
                float dx = xv - av.x;
                float sv = fmaf(av.z, dx, av.y);
                float tv = fmaf(st,   dx, av.w);
                float logs = fmaf(fast_tanh(sv), sw, sb);
                zn[e] = fmaf(__expf(logs), x2v[e], tv);
                lg[e] = logs;
            }
            SZ1[lq] = z2;                                     // new z1 = x1
            SZ2[lq] = make_float4(zn[0], zn[1], zn[2], zn[3]);
            SLD[lq] = make_float4(ld.x + lg[0], ld.y + lg[1],
                                  ld.z + lg[2], ld.w + lg[3]);
        }
    }
    __syncthreads();

    float4* o4  = (float4*)out;
    float4* ld4 = (float4*)(out + 8 * (size_t)nquads);
    for (int lq = tid; lq < nq; lq += MAIN_T) {
        int Q = q0 + lq;
        float4 z1 = SZ1[lq], z2 = SZ2[lq];
        o4[2 * Q]     = make_float4(z1.x, z2.x, z1.y, z2.y);
        o4[2 * Q + 1] = make_float4(z1.z, z2.z, z1.w, z2.w);
        ld4[Q] = SLD[lq];
    }
}

extern "C" void kernel_launch(void* const* d_in, const int* in_sizes, int n_in,
                              void* d_out, int out_size) {
    const float* x       = (const float*)d_in[0];
    const float* scale_w = (const float*)d_in[1];
    const float* scale_b = (const float*)d_in[2];
    const float* sW1 = (const float*)d_in[3];
    const float* sb1 = (const float*)d_in[4];
    const float* sW2 = (const float*)d_in[5];
    const float* sb2 = (const float*)d_in[6];
    const float* sW3 = (const float*)d_in[7];
    const float* sb3 = (const float*)d_in[8];
    const float* tW1 = (const float*)d_in[9];
    const float* tb1 = (const float*)d_in[10];
    const float* tW2 = (const float*)d_in[11];
    const float* tb2 = (const float*)d_in[12];
    const float* tW3 = (const float*)d_in[13];
    const float* tb3 = (const float*)d_in[14];
    float* out = (float*)d_out;

    int nquads = in_sizes[0] / 8;
    int grid = (nquads + QPC - 1) / QPC;   // 296 for N=4194304

    const int smem_main = MAXK * 16 + 3 * QPC * 16 + 2 * MAXK * 4 + GCELLS * 2;
    cudaFuncSetAttribute(flow_kernel, cudaFuncAttributeMaxDynamicSharedMemorySize, smem_main);

    prep_a_kernel<<<NLAYERS, PREPA_T>>>(sW1, sb1, sW2, sb2, tW1, tb1, tW2, tb2);
    prep_b_kernel<<<NLAYERS * SPLIT, PREPB_T>>>(sW1, sb1, sW2, sb2, sW3, sb3,
                                                tW1, tb1, tW2, tb2, tW3, tb3);
    flow_kernel<<<grid, MAIN_T, smem_main>>>(x, scale_w, scale_b, out, nquads);
}

// round 15
// speedup vs baseline: 1.6736x; 1.1245x over previous
#include <cuda_runtime.h>
#include <cstdint>
#include <math_constants.h>

// RealNVP, exact piecewise-linear collapse.
// R15 over R14 (315.9us = 40.2 prep_a + ~275 flow/prep_b):
//  (1) prep_a serial tid==0 insertion sorts (the 40us!) replaced by a parallel
//      rank-sort over the <=32 L1 knees (O(n^2) compares, fully parallel).
//  (2) GCELLS 2048 -> 4096: halves impure-cell rate and walk length in flow.
// Flow structure unchanged (R11 smem state + pure-cell flag + clamped walk).

#define NLAYERS 15
#define MAXK    1280          // merged knees bound: 2*560=1120
#define KSORT   2048
#define GCELLS  4096
#define PREPA_T 512
#define PREPB_T 256
#define SPLIT   8             // prep_b blocks per layer
#define MAIN_T  1024
#define QPC     3543          // quads per CTA; 296 CTAs for N=4194304

__device__ float  g_B [NLAYERS][MAXK];      // knots; B[0]=-inf, +inf padded
__device__ float4 g_AV[NLAYERS][MAXK];      // (A, Vs, Ss, Vt)
__device__ float  g_St[NLAYERS][MAXK];      // St
__device__ unsigned short g_grid[NLAYERS][GCELLS];  // bit15=impure, low15=idx
__device__ float  g_x0[NLAYERS], g_invh[NLAYERS], g_h[NLAYERS];
__device__ int    g_m[NLAYERS];

__device__ __forceinline__ float fast_tanh(float x) {
    float e = __expf(2.0f * x);
    float r = __frcp_rn(e + 1.0f);
    return fmaf(-2.0f, r, 1.0f);
}

// ---------------------------------------------------------------------------
// prep_a: one block per layer. Knees -> bitonic sort -> B, m, grid params.
// ---------------------------------------------------------------------------
__global__ __launch_bounds__(PREPA_T, 1) void prep_a_kernel(
    const float* __restrict__ sW1, const float* __restrict__ sb1,
    const float* __restrict__ sW2, const float* __restrict__ sb2,
    const float* __restrict__ tW1, const float* __restrict__ tb1,
    const float* __restrict__ tW2, const float* __restrict__ tb2)
{
    __shared__ float w1[2][32], b1[2][32], W2s[2][512], b2s[2][16];
    __shared__ float K[KSORT];
    __shared__ float X[34];
    __shared__ float tmpX[32];
    __shared__ int   vflag[32];
    __shared__ int cnt, m1s;

    int tid = threadIdx.x;
    int l = blockIdx.x;

    for (int i = tid; i < 32; i += PREPA_T) {
        w1[0][i] = sW1[l*32+i]; b1[0][i] = sb1[l*32+i];
        w1[1][i] = tW1[l*32+i]; b1[1][i] = tb1[l*32+i];
    }
    for (int i = tid; i < 512; i += PREPA_T) {
        W2s[0][i] = sW2[l*512+i]; W2s[1][i] = tW2[l*512+i];
    }
    for (int i = tid; i < 16; i += PREPA_T) {
        b2s[0][i] = sb2[l*16+i]; b2s[1][i] = tb2[l*16+i];
    }
    if (tid == 0) cnt = 0;
    for (int i = tid; i < KSORT; i += PREPA_T) K[i] = CUDART_INF_F;
    __syncthreads();

    for (int p = 0; p < 2; p++) {
        int c0 = cnt;                      // uniform (post-sync)
        // parallel rank-sort of the <=32 L1 knees
        if (tid < 32) {
            float w = w1[p][tid], b = b1[p][tid];
            bool valid = (w != 0.0f);
            tmpX[tid] = valid ? (-b / w) : 0.0f;
            vflag[tid] = valid ? 1 : 0;
        }
        __syncthreads();
        if (tid < 32 && vflag[tid]) {
            float xi = tmpX[tid];
            int rank = 0;
            for (int j = 0; j < 32; j++) {
                if (vflag[j]) {
                    float xj = tmpX[j];
                    if (xj < xi || (xj == xi && j < tid)) rank++;
                }
            }
            X[rank + 1] = xi;
        }
        if (tid == 0) {
            int m1 = 0;
            for (int j = 0; j < 32; j++) m1 += vflag[j];
            m1s = m1;
            X[0] = -CUDART_INF_F;
        }
        __syncthreads();
        int m1 = m1s;
        if (tid == 0) {
            X[m1 + 1] = CUDART_INF_F;
            cnt = c0 + m1;
        }
        if (tid < 32 && tid < m1) K[c0 + tid] = X[tid + 1];
        __syncthreads();

        // layer-2 knees: a2_j linear within each L1 interval -> <=1 root each
        int ntask = (m1 + 1) * 16;
        for (int t = tid; t < ntask; t += PREPA_T) {
            int iv = t >> 4, j = t & 15;
            float lo = X[iv], hi = X[iv + 1];
            float xm;
            if (!isfinite(lo) && !isfinite(hi)) xm = 0.0f;
            else if (!isfinite(lo)) xm = hi - 1.0f;
            else if (!isfinite(hi)) xm = lo + 1.0f;
            else xm = 0.5f * (lo + hi);
            float c = b2s[p][j], d = 0.0f;
            for (int i = 0; i < 32; i++) {
                float pre = fmaf(w1[p][i], xm, b1[p][i]);
                float s1 = (pre >= 0.0f) ? 1.0f : 0.01f;
                float wij = W2s[p][i * 16 + j];
                d = fmaf(wij * s1, w1[p][i], d);
                c = fmaf(wij * s1, b1[p][i], c);
            }
            if (d != 0.0f) {
                float r = -c / d;
                if (isfinite(r) && r > lo && r < hi) {
                    int pos = atomicAdd(&cnt, 1);
                    K[pos] = r;
                }
            }
        }
        __syncthreads();
    }
    int m = cnt;
    if (m > MAXK - 2) m = MAXK - 2;        // paranoia clamp (bound is 1120)

    // dynamic-width bitonic sort: width Ks = next_pow2(m) (rest are +inf)
    int Ks = 2;
    while (Ks < m) Ks <<= 1;
    for (int k = 2; k <= Ks; k <<= 1) {
        for (int j = k >> 1; j > 0; j >>= 1) {
            __syncthreads();
            for (int t = tid; t < (Ks >> 1); t += PREPA_T) {
                int i = ((t / j) * (j << 1)) + (t & (j - 1));
                int q = i + j;
                float a = K[i], b = K[q];
                bool up = ((i & k) == 0);
                if (up ? (a > b) : (a < b)) { K[i] = b; K[q] = a; }
            }
        }
    }
    __syncthreads();

    for (int kk = tid; kk < MAXK; kk += PREPA_T) {
        float v = (kk == 0) ? -CUDART_INF_F : (kk <= m ? K[kk - 1] : CUDART_INF_F);
        g_B[l][kk] = v;
    }
    if (tid == 0) {
        g_m[l] = m;
        float x0 = (m >= 1) ? K[0] : 0.0f;
        float xr = (m >= 1) ? K[m - 1] : 0.0f;
        float invh = (m >= 2 && xr > x0) ? (float)GCELLS / (xr - x0) : 0.0f;
        g_x0[l] = x0;
        g_invh[l] = invh;
        g_h[l] = (invh > 0.0f) ? (xr - x0) / (float)GCELLS : 0.0f;
    }
}

// ---------------------------------------------------------------------------
// prep_b: SPLIT blocks per layer. Per-segment payloads + grid cells.
// ---------------------------------------------------------------------------
__global__ __launch_bounds__(PREPB_T, 1) void prep_b_kernel(
    const float* __restrict__ sW1, const float* __restrict__ sb1,
    const float* __restrict__ sW2, const float* __restrict__ sb2,
    const float* __restrict__ sW3, const float* __restrict__ sb3,
    const float* __restrict__ tW1, const float* __restrict__ tb1,
    const float* __restrict__ tW2, const float* __restrict__ tb2,
    const float* __restrict__ tW3, const float* __restrict__ tb3)
{
    __shared__ float w1[2][32], b1[2][32], W2s[2][512], b2s[2][16], w3s[2][16], b3s[2];

    int tid = threadIdx.x;
    int l = blockIdx.x / SPLIT;
    int s = blockIdx.x % SPLIT;

    for (int i = tid; i < 32; i += PREPB_T) {
        w1[0][i] = sW1[l*32+i]; b1[0][i] = sb1[l*32+i];
        w1[1][i] = tW1[l*32+i]; b1[1][i] = tb1[l*32+i];
    }
    for (int i = tid; i < 512; i += PREPB_T) {
        W2s[0][i] = sW2[l*512+i]; W2s[1][i] = tW2[l*512+i];
    }
    for (int i = tid; i < 16; i += PREPB_T) {
        b2s[0][i] = sb2[l*16+i]; w3s[0][i] = sW3[l*16+i];
        b2s[1][i] = tb2[l*16+i]; w3s[1][i] = tW3[l*16+i];
    }
    if (tid == 0) { b3s[0] = sb3[l]; b3s[1] = tb3[l]; }
    __syncthreads();

    int m = g_m[l];
    const float* B = g_B[l];

    const int CH = MAXK / SPLIT;                  // 160
    for (int idx = s * CH + tid; idx < (s + 1) * CH; idx += PREPB_T) {
        if (idx > m) {
            g_AV[l][idx] = make_float4(0.f, 0.f, 0.f, 0.f);
            g_St[l][idx] = 0.f;
            continue;
        }
        float Bl = B[idx];
        float Br = B[idx + 1];
        float A  = isfinite(Bl) ? Bl : ((m >= 1) ? B[1] : 0.0f);
        float xm;
        if (!isfinite(Bl) && !isfinite(Br)) xm = 0.0f;
        else if (!isfinite(Bl)) xm = Br - 1.0f;
        else if (!isfinite(Br)) xm = Bl + 1.0f;
        else { xm = 0.5f * (Bl + Br); if (!(xm > Bl && xm < Br)) xm = Bl; }

        float V[2], S[2];
        for (int p = 0; p < 2; p++) {
            float acc[16];
#pragma unroll
            for (int j = 0; j < 16; j++) acc[j] = b2s[p][j];
            for (int i = 0; i < 32; i++) {
                float pre = fmaf(w1[p][i], A, b1[p][i]);
                float h = fmaxf(pre, 0.01f * pre);
#pragma unroll
                for (int j = 0; j < 16; j++) acc[j] = fmaf(h, W2s[p][i * 16 + j], acc[j]);
            }
            float Vv = b3s[p];
#pragma unroll
            for (int j = 0; j < 16; j++) {
                float hh = fmaxf(acc[j], 0.01f * acc[j]);
                Vv = fmaf(hh, w3s[p][j], Vv);
            }
            float a2[16], dd[16];
#pragma unroll
            for (int j = 0; j < 16; j++) { a2[j] = b2s[p][j]; dd[j] = 0.0f; }
            for (int i = 0; i < 32; i++) {
                float pre = fmaf(w1[p][i], xm, b1[p][i]);
                float s1 = (pre >= 0.0f) ? 1.0f : 0.01f;
                float h = s1 * pre;
                float dh = s1 * w1[p][i];
#pragma unroll
                for (int j = 0; j < 16; j++) {
                    float wij = W2s[p][i * 16 + j];
                    a2[j] = fmaf(h, wij, a2[j]);
                    dd[j] = fmaf(dh, wij, dd[j]);
                }
            }
            float Sv = 0.0f;
#pragma unroll
            for (int j = 0; j < 16; j++) {
                float s2 = (a2[j] >= 0.0f) ? 1.0f : 0.01f;
                Sv = fmaf(w3s[p][j] * s2, dd[j], Sv);
            }
            V[p] = Vv; S[p] = Sv;
        }
        g_AV[l][idx] = make_float4(A, V[0], S[0], V[1]);
        g_St[l][idx] = S[1];
    }

    const int GC = GCELLS / SPLIT;                // 512
    float x0 = g_x0[l], h = g_h[l];
    float wd = 0.01f * h;
    for (int g = s * GC + tid; g < (s + 1) * GC; g += PREPB_T) {
        int ilo = 0, ihi = 0;
        if (m >= 1) {
            float xlo = x0 + (float)g * h - wd;
            float xhi = x0 + (float)(g + 1) * h + wd;
            int lo = 0, hi = m;
            while (lo < hi) { int mid = (lo + hi + 1) >> 1; if (B[mid] <= xlo) lo = mid; else hi = mid - 1; }
            ilo = lo;
            lo = 0; hi = m;
            while (lo < hi) { int mid = (lo + hi + 1) >> 1; if (B[mid] <= xhi) lo = mid; else hi = mid - 1; }
            ihi = lo;
        }
        bool impure = (ilo != ihi) || (g == 0) || (g == GCELLS - 1);
        g_grid[l][g] = (unsigned short)(ilo | (impure ? 0x8000 : 0));
    }
}

// ---------------------------------------------------------------------------
// Flow kernel: R11 structure (smem state) + pure-cell fast path + clamped walk.
// ---------------------------------------------------------------------------
extern __shared__ float4 smb[];

__global__ __launch_bounds__(MAIN_T, 1) void flow_kernel(
    const float* __restrict__ x,
    const float* __restrict__ scale_w, const float* __restrict__ scale_b,
    float* __restrict__ out, int nquads)
{
    float4* AVs = smb;                     // MAXK float4
    float4* SZ1 = AVs + MAXK;              // QPC
    float4* SZ2 = SZ1 + QPC;
    float4* SLD = SZ2 + QPC;
    float*  Bs  = (float*)(SLD + QPC);     // MAXK
    float*  Sts = Bs + MAXK;               // MAXK
    unsigned short* Gs = (unsigned short*)(Sts + MAXK);  // GCELLS

    int tid = threadIdx.x;
    int q0 = blockIdx.x * QPC;
    int nq = nquads - q0;
    if (nq > QPC) nq = QPC;

    const float4* x4 = (const float4*)x;
    for (int lq = tid; lq < nq; lq += MAIN_T) {
        int Q = q0 + lq;
        float4 a = x4[2 * Q], b = x4[2 * Q + 1];
        SZ1[lq] = make_float4(a.y, a.w, b.y, b.w);   // x[:,1]
        SZ2[lq] = make_float4(a.x, a.z, b.x, b.z);   // x[:,0]
        SLD[lq] = make_float4(0.f, 0.f, 0.f, 0.f);
    }

    for (int l = 0; l < NLAYERS; l++) {
        __syncthreads();
        {
            const float*  gB = g_B[l];
            const float4* gA = g_AV[l];
            const float*  gS = g_St[l];
            const unsigned short* gG = g_grid[l];
            for (int k = tid; k < MAXK; k += MAIN_T) {
                Bs[k] = gB[k]; AVs[k] = gA[k]; Sts[k] = gS[k];
            }
            for (int g = tid; g < GCELLS; g += MAIN_T) Gs[g] = gG[g];
        }
        int mloc = g_m[l];
        float x0 = g_x0[l], invh = g_invh[l];
        float sw = scale_w[l], sb = scale_b[l];
        __syncthreads();

        for (int lq = tid; lq < nq; lq += MAIN_T) {
            float4 z1 = SZ1[lq], z2 = SZ2[lq], ld = SLD[lq];
            float x1v[4] = {z2.x, z2.y, z2.z, z2.w};
            float x2v[4] = {z1.x, z1.y, z1.z, z1.w};
            float zn[4], lg[4];
#pragma unroll
            for (int e = 0; e < 4; e++) {
                float xv = x1v[e];
                int c = (int)((xv - x0) * invh);
                c = min(max(c, 0), GCELLS - 1);
                unsigned int e16 = Gs[c];
                int idx = e16 & 0x7FFF;
                if (e16 & 0x8000u) {
                    while (idx < mloc && Bs[idx + 1] <= xv) idx++;
                }
                float4 av = AVs[idx];
                float st = Sts[idx];
                float dx = xv - av.x;
                float sv = fmaf(av.z, dx, av.y);
                float tv = fmaf(st,   dx, av.w);
                float logs = fmaf(fast_tanh(sv), sw, sb);
                zn[e] = fmaf(__expf(logs), x2v[e], tv);
                lg[e] = logs;
            }
            SZ1[lq] = z2;                                     // new z1 = x1
            SZ2[lq] = make_float4(zn[0], zn[1], zn[2], zn[3]);
            SLD[lq] = make_float4(ld.x + lg[0], ld.y + lg[1],
                                  ld.z + lg[2], ld.w + lg[3]);
        }
    }
    __syncthreads();

    float4* o4  = (float4*)out;
    float4* ld4 = (float4*)(out + 8 * (size_t)nquads);
    for (int lq = tid; lq < nq; lq += MAIN_T) {
        int Q = q0 + lq;
        float4 z1 = SZ1[lq], z2 = SZ2[lq];
        o4[2 * Q]     = make_float4(z1.x, z2.x, z1.y, z2.y);
        o4[2 * Q + 1] = make_float4(z1.z, z2.z, z1.w, z2.w);
        ld4[Q] = SLD[lq];
    }
}

extern "C" void kernel_launch(void* const* d_in, const int* in_sizes, int n_in,
                              void* d_out, int out_size) {
    const float* x       = (const float*)d_in[0];
    const float* scale_w = (const float*)d_in[1];
    const float* scale_b = (const float*)d_in[2];
    const float* sW1 = (const float*)d_in[3];
    const float* sb1 = (const float*)d_in[4];
    const float* sW2 = (const float*)d_in[5];
    const float* sb2 = (const float*)d_in[6];
    const float* sW3 = (const float*)d_in[7];
    const float* sb3 = (const float*)d_in[8];
    const float* tW1 = (const float*)d_in[9];
    const float* tb1 = (const float*)d_in[10];
    const float* tW2 = (const float*)d_in[11];
    const float* tb2 = (const float*)d_in[12];
    const float* tW3 = (const float*)d_in[13];
    const float* tb3 = (const float*)d_in[14];
    float* out = (float*)d_out;

    int nquads = in_sizes[0] / 8;
    int grid = (nquads + QPC - 1) / QPC;   // 296 for N=4194304

    const int smem_main = MAXK * 16 + 3 * QPC * 16 + 2 * MAXK * 4 + GCELLS * 2;
    cudaFuncSetAttribute(flow_kernel, cudaFuncAttributeMaxDynamicSharedMemorySize, smem_main);

    prep_a_kernel<<<NLAYERS, PREPA_T>>>(sW1, sb1, sW2, sb2, tW1, tb1, tW2, tb2);
    prep_b_kernel<<<NLAYERS * SPLIT, PREPB_T>>>(sW1, sb1, sW2, sb2, sW3, sb3,
                                                tW1, tb1, tW2, tb2, tW3, tb3);
    flow_kernel<<<grid, MAIN_T, smem_main>>>(x, scale_w, scale_b, out, nquads);
}

// round 16
// speedup vs baseline: 1.8966x; 1.1332x over previous
#include <cuda_runtime.h>
#include <cstdint>
#include <math_constants.h>

// RealNVP, exact piecewise-linear collapse.
// R16 over R15 (280.9us):
//  (1) intercept-form payload: one float4 (Ss, Cs, St, Ct), C = V - S*A
//      precomputed -> kills the St LDS, the dx subtract, and A handling.
//  (2) ping-pong state buffers: z1_{l+1}=z2_l by pointer swap (one fewer
//      16B smem store per quad-layer).
//  (3) GCELLS 4096 -> 8192: impure-warp rate 73% -> ~48%.

#define NLAYERS 15
#define MAXK    1280          // merged knees bound: 2*560=1120
#define KSORT   2048
#define GCELLS  8192
#define PREPA_T 512
#define PREPB_T 256
#define SPLIT   8             // prep_b blocks per layer
#define MAIN_T  1024
#define QPC     3543          // quads per CTA; 296 CTAs for N=4194304

__device__ float  g_B [NLAYERS][MAXK];      // knots; B[0]=-inf, +inf padded
__device__ float4 g_AV[NLAYERS][MAXK];      // (Ss, Cs, St, Ct) intercept form
__device__ unsigned short g_grid[NLAYERS][GCELLS];  // bit15=impure, low15=idx
__device__ float  g_x0[NLAYERS], g_invh[NLAYERS], g_h[NLAYERS];
__device__ int    g_m[NLAYERS];

__device__ __forceinline__ float fast_tanh(float x) {
    float e = __expf(2.0f * x);
    float r = __frcp_rn(e + 1.0f);
    return fmaf(-2.0f, r, 1.0f);
}

// ---------------------------------------------------------------------------
// prep_a: one block per layer. Knees -> bitonic sort -> B, m, grid params.
// ---------------------------------------------------------------------------
__global__ __launch_bounds__(PREPA_T, 1) void prep_a_kernel(
    const float* __restrict__ sW1, const float* __restrict__ sb1,
    const float* __restrict__ sW2, const float* __restrict__ sb2,
    const float* __restrict__ tW1, const float* __restrict__ tb1,
    const float* __restrict__ tW2, const float* __restrict__ tb2)
{
    __shared__ float w1[2][32], b1[2][32], W2s[2][512], b2s[2][16];
    __shared__ float K[KSORT];
    __shared__ float X[34];
    __shared__ float tmpX[32];
    __shared__ int   vflag[32];
    __shared__ int cnt, m1s;

    int tid = threadIdx.x;
    int l = blockIdx.x;

    for (int i = tid; i < 32; i += PREPA_T) {
        w1[0][i] = sW1[l*32+i]; b1[0][i] = sb1[l*32+i];
        w1[1][i] = tW1[l*32+i]; b1[1][i] = tb1[l*32+i];
    }
    for (int i = tid; i < 512; i += PREPA_T) {
        W2s[0][i] = sW2[l*512+i]; W2s[1][i] = tW2[l*512+i];
    }
    for (int i = tid; i < 16; i += PREPA_T) {
        b2s[0][i] = sb2[l*16+i]; b2s[1][i] = tb2[l*16+i];
    }
    if (tid == 0) cnt = 0;
    for (int i = tid; i < KSORT; i += PREPA_T) K[i] = CUDART_INF_F;
    __syncthreads();

    for (int p = 0; p < 2; p++) {
        int c0 = cnt;                      // uniform (post-sync)
        if (tid < 32) {
            float w = w1[p][tid], b = b1[p][tid];
            bool valid = (w != 0.0f);
            tmpX[tid] = valid ? (-b / w) : 0.0f;
            vflag[tid] = valid ? 1 : 0;
        }
        __syncthreads();
        if (tid < 32 && vflag[tid]) {
            float xi = tmpX[tid];
            int rank = 0;
            for (int j = 0; j < 32; j++) {
                if (vflag[j]) {
                    float xj = tmpX[j];
                    if (xj < xi || (xj == xi && j < tid)) rank++;
                }
            }
            X[rank + 1] = xi;
        }
        if (tid == 0) {
            int m1 = 0;
            for (int j = 0; j < 32; j++) m1 += vflag[j];
            m1s = m1;
            X[0] = -CUDART_INF_F;
        }
        __syncthreads();
        int m1 = m1s;
        if (tid == 0) {
            X[m1 + 1] = CUDART_INF_F;
            cnt = c0 + m1;
        }
        if (tid < 32 && tid < m1) K[c0 + tid] = X[tid + 1];
        __syncthreads();

        int ntask = (m1 + 1) * 16;
        for (int t = tid; t < ntask; t += PREPA_T) {
            int iv = t >> 4, j = t & 15;
            float lo = X[iv], hi = X[iv + 1];
            float xm;
            if (!isfinite(lo) && !isfinite(hi)) xm = 0.0f;
            else if (!isfinite(lo)) xm = hi - 1.0f;
            else if (!isfinite(hi)) xm = lo + 1.0f;
            else xm = 0.5f * (lo + hi);
            float c = b2s[p][j], d = 0.0f;
            for (int i = 0; i < 32; i++) {
                float pre = fmaf(w1[p][i], xm, b1[p][i]);
                float s1 = (pre >= 0.0f) ? 1.0f : 0.01f;
                float wij = W2s[p][i * 16 + j];
                d = fmaf(wij * s1, w1[p][i], d);
                c = fmaf(wij * s1, b1[p][i], c);
            }
            if (d != 0.0f) {
                float r = -c / d;
                if (isfinite(r) && r > lo && r < hi) {
                    int pos = atomicAdd(&cnt, 1);
                    K[pos] = r;
                }
            }
        }
        __syncthreads();
    }
    int m = cnt;
    if (m > MAXK - 2) m = MAXK - 2;        // paranoia clamp (bound is 1120)

    int Ks = 2;
    while (Ks < m) Ks <<= 1;
    for (int k = 2; k <= Ks; k <<= 1) {
        for (int j = k >> 1; j > 0; j >>= 1) {
            __syncthreads();
            for (int t = tid; t < (Ks >> 1); t += PREPA_T) {
                int i = ((t / j) * (j << 1)) + (t & (j - 1));
                int q = i + j;
                float a = K[i], b = K[q];
                bool up = ((i & k) == 0);
                if (up ? (a > b) : (a < b)) { K[i] = b; K[q] = a; }
            }
        }
    }
    __syncthreads();

    for (int kk = tid; kk < MAXK; kk += PREPA_T) {
        float v = (kk == 0) ? -CUDART_INF_F : (kk <= m ? K[kk - 1] : CUDART_INF_F);
        g_B[l][kk] = v;
    }
    if (tid == 0) {
        g_m[l] = m;
        float x0 = (m >= 1) ? K[0] : 0.0f;
        float xr = (m >= 1) ? K[m - 1] : 0.0f;
        float invh = (m >= 2 && xr > x0) ? (float)GCELLS / (xr - x0) : 0.0f;
        g_x0[l] = x0;
        g_invh[l] = invh;
        g_h[l] = (invh > 0.0f) ? (xr - x0) / (float)GCELLS : 0.0f;
    }
}

// ---------------------------------------------------------------------------
// prep_b: SPLIT blocks per layer. Per-segment intercept payloads + grid cells.
// ---------------------------------------------------------------------------
__global__ __launch_bounds__(PREPB_T, 1) void prep_b_kernel(
    const float* __restrict__ sW1, const float* __restrict__ sb1,
    const float* __restrict__ sW2, const float* __restrict__ sb2,
    const float* __restrict__ sW3, const float* __restrict__ sb3,
    const float* __restrict__ tW1, const float* __restrict__ tb1,
    const float* __restrict__ tW2, const float* __restrict__ tb2,
    const float* __restrict__ tW3, const float* __restrict__ tb3)
{
    __shared__ float w1[2][32], b1[2][32], W2s[2][512], b2s[2][16], w3s[2][16], b3s[2];

    int tid = threadIdx.x;
    int l = blockIdx.x / SPLIT;
    int s = blockIdx.x % SPLIT;

    for (int i = tid; i < 32; i += PREPB_T) {
        w1[0][i] = sW1[l*32+i]; b1[0][i] = sb1[l*32+i];
        w1[1][i] = tW1[l*32+i]; b1[1][i] = tb1[l*32+i];
    }
    for (int i = tid; i < 512; i += PREPB_T) {
        W2s[0][i] = sW2[l*512+i]; W2s[1][i] = tW2[l*512+i];
    }
    for (int i = tid; i < 16; i += PREPB_T) {
        b2s[0][i] = sb2[l*16+i]; w3s[0][i] = sW3[l*16+i];
        b2s[1][i] = tb2[l*16+i]; w3s[1][i] = tW3[l*16+i];
    }
    if (tid == 0) { b3s[0] = sb3[l]; b3s[1] = tb3[l]; }
    __syncthreads();

    int m = g_m[l];
    const float* B = g_B[l];

    const int CH = MAXK / SPLIT;                  // 160
    for (int idx = s * CH + tid; idx < (s + 1) * CH; idx += PREPB_T) {
        if (idx > m) {
            g_AV[l][idx] = make_float4(0.f, 0.f, 0.f, 0.f);
            continue;
        }
        float Bl = B[idx];
        float Br = B[idx + 1];
        float A  = isfinite(Bl) ? Bl : ((m >= 1) ? B[1] : 0.0f);
        float xm;
        if (!isfinite(Bl) && !isfinite(Br)) xm = 0.0f;
        else if (!isfinite(Bl)) xm = Br - 1.0f;
        else if (!isfinite(Br)) xm = Bl + 1.0f;
        else { xm = 0.5f * (Bl + Br); if (!(xm > Bl && xm < Br)) xm = Bl; }

        float V[2], S[2];
        for (int p = 0; p < 2; p++) {
            float acc[16];
#pragma unroll
            for (int j = 0; j < 16; j++) acc[j] = b2s[p][j];
            for (int i = 0; i < 32; i++) {
                float pre = fmaf(w1[p][i], A, b1[p][i]);
                float h = fmaxf(pre, 0.01f * pre);
#pragma unroll
                for (int j = 0; j < 16; j++) acc[j] = fmaf(h, W2s[p][i * 16 + j], acc[j]);
            }
            float Vv = b3s[p];
#pragma unroll
            for (int j = 0; j < 16; j++) {
                float hh = fmaxf(acc[j], 0.01f * acc[j]);
                Vv = fmaf(hh, w3s[p][j], Vv);
            }
            float a2[16], dd[16];
#pragma unroll
            for (int j = 0; j < 16; j++) { a2[j] = b2s[p][j]; dd[j] = 0.0f; }
            for (int i = 0; i < 32; i++) {
                float pre = fmaf(w1[p][i], xm, b1[p][i]);
                float s1 = (pre >= 0.0f) ? 1.0f : 0.01f;
                float h = s1 * pre;
                float dh = s1 * w1[p][i];
#pragma unroll
                for (int j = 0; j < 16; j++) {
                    float wij = W2s[p][i * 16 + j];
                    a2[j] = fmaf(h, wij, a2[j]);
                    dd[j] = fmaf(dh, wij, dd[j]);
                }
            }
            float Sv = 0.0f;
#pragma unroll
            for (int j = 0; j < 16; j++) {
                float s2 = (a2[j] >= 0.0f) ? 1.0f : 0.01f;
                Sv = fmaf(w3s[p][j] * s2, dd[j], Sv);
            }
            V[p] = Vv; S[p] = Sv;
        }
        // intercept form: C = V - S*A ; eval is fma(S, x, C)
        float Cs = fmaf(-S[0], A, V[0]);
        float Ct = fmaf(-S[1], A, V[1]);
        g_AV[l][idx] = make_float4(S[0], Cs, S[1], Ct);
    }

    const int GC = GCELLS / SPLIT;                // 1024
    float x0 = g_x0[l], h = g_h[l];
    float wd = 0.01f * h;
    for (int g = s * GC + tid; g < (s + 1) * GC; g += PREPB_T) {
        int ilo = 0, ihi = 0;
        if (m >= 1) {
            float xlo = x0 + (float)g * h - wd;
            float xhi = x0 + (float)(g + 1) * h + wd;
            int lo = 0, hi = m;
            while (lo < hi) { int mid = (lo + hi + 1) >> 1; if (B[mid] <= xlo) lo = mid; else hi = mid - 1; }
            ilo = lo;
            lo = 0; hi = m;
            while (lo < hi) { int mid = (lo + hi + 1) >> 1; if (B[mid] <= xhi) lo = mid; else hi = mid - 1; }
            ihi = lo;
        }
        bool impure = (ilo != ihi) || (g == 0) || (g == GCELLS - 1);
        g_grid[l][g] = (unsigned short)(ilo | (impure ? 0x8000 : 0));
    }
}

// ---------------------------------------------------------------------------
// Flow kernel: smem ping-pong state + pure-cell fast path + intercept eval.
// ---------------------------------------------------------------------------
extern __shared__ float4 smb[];

__global__ __launch_bounds__(MAIN_T, 1) void flow_kernel(
    const float* __restrict__ x,
    const float* __restrict__ scale_w, const float* __restrict__ scale_b,
    float* __restrict__ out, int nquads)
{
    float4* AVs = smb;                     // MAXK float4
    float4* SZa = AVs + MAXK;              // QPC  (ping)
    float4* SZb = SZa + QPC;               // QPC  (pong)
    float4* SLD = SZb + QPC;               // QPC
    float*  Bs  = (float*)(SLD + QPC);     // MAXK
    unsigned short* Gs = (unsigned short*)(Bs + MAXK);  // GCELLS

    int tid = threadIdx.x;
    int q0 = blockIdx.x * QPC;
    int nq = nquads - q0;
    if (nq > QPC) nq = QPC;

    // P holds z2 (x1 source), Q holds z1 (x2 source)
    float4* P = SZa;
    float4* Q = SZb;

    const float4* x4 = (const float4*)x;
    for (int lq = tid; lq < nq; lq += MAIN_T) {
        int Qi = q0 + lq;
        float4 a = x4[2 * Qi], b = x4[2 * Qi + 1];
        Q[lq] = make_float4(a.y, a.w, b.y, b.w);   // z1 = x[:,1]
        P[lq] = make_float4(a.x, a.z, b.x, b.z);   // z2 = x[:,0]
        SLD[lq] = make_float4(0.f, 0.f, 0.f, 0.f);
    }

    for (int l = 0; l < NLAYERS; l++) {
        __syncthreads();
        {
            const float*  gB = g_B[l];
            const float4* gA = g_AV[l];
            const unsigned short* gG = g_grid[l];
            for (int k = tid; k < MAXK; k += MAIN_T) {
                Bs[k] = gB[k]; AVs[k] = gA[k];
            }
            for (int g = tid; g < GCELLS; g += MAIN_T) Gs[g] = gG[g];
        }
        int mloc = g_m[l];
        float x0 = g_x0[l], invh = g_invh[l];
        float sw = scale_w[l], sb = scale_b[l];
        __syncthreads();

        for (int lq = tid; lq < nq; lq += MAIN_T) {
            float4 z2 = P[lq], z1 = Q[lq], ld = SLD[lq];
            float x1v[4] = {z2.x, z2.y, z2.z, z2.w};
            float x2v[4] = {z1.x, z1.y, z1.z, z1.w};
            float zn[4], lg[4];
#pragma unroll
            for (int e = 0; e < 4; e++) {
                float xv = x1v[e];
                int c = (int)((xv - x0) * invh);
                c = min(max(c, 0), GCELLS - 1);
                unsigned int e16 = Gs[c];
                int idx = e16 & 0x7FFF;
                if (e16 & 0x8000u) {
                    while (idx < mloc && Bs[idx + 1] <= xv) idx++;
                }
                float4 av = AVs[idx];
                float sv = fmaf(av.x, xv, av.y);
                float tv = fmaf(av.z, xv, av.w);
                float logs = fmaf(fast_tanh(sv), sw, sb);
                zn[e] = fmaf(__expf(logs), x2v[e], tv);
                lg[e] = logs;
            }
            Q[lq] = make_float4(zn[0], zn[1], zn[2], zn[3]);  // new z2
            SLD[lq] = make_float4(ld.x + lg[0], ld.y + lg[1],
                                  ld.z + lg[2], ld.w + lg[3]);
        }
        // swap roles: new z1 = old z2 (P), new z2 in Q
        float4* tmp = P; P = Q; Q = tmp;
    }
    __syncthreads();

    float4* o4  = (float4*)out;
    float4* ld4 = (float4*)(out + 8 * (size_t)nquads);
    for (int lq = tid; lq < nq; lq += MAIN_T) {
        int Qi = q0 + lq;
        float4 z2 = P[lq], z1 = Q[lq];     // P=z2_final, Q=z1_final
        o4[2 * Qi]     = make_float4(z1.x, z2.x, z1.y, z2.y);
        o4[2 * Qi + 1] = make_float4(z1.z, z2.z, z1.w, z2.w);
        ld4[Qi] = SLD[lq];
    }
}

extern "C" void kernel_launch(void* const* d_in, const int* in_sizes, int n_in,
                              void* d_out, int out_size) {
    const float* x       = (const float*)d_in[0];
    const float* scale_w = (const float*)d_in[1];
    const float* scale_b = (const float*)d_in[2];
    const float* sW1 = (const float*)d_in[3];
    const float* sb1 = (const float*)d_in[4];
    const float* sW2 = (const float*)d_in[5];
    const float* sb2 = (const float*)d_in[6];
    const float* sW3 = (const float*)d_in[7];
    const float* sb3 = (const float*)d_in[8];
    const float* tW1 = (const float*)d_in[9];
    const float* tb1 = (const float*)d_in[10];
    const float* tW2 = (const float*)d_in[11];
    const float* tb2 = (const float*)d_in[12];
    const float* tW3 = (const float*)d_in[13];
    const float* tb3 = (const float*)d_in[14];
    float* out = (float*)d_out;

    int nquads = in_sizes[0] / 8;
    int grid = (nquads + QPC - 1) / QPC;   // 296 for N=4194304

    // smem: AV float4 + 3*QPC float4 + Bs float + grid u16 = 212,048 B
    const int smem_main = MAXK * 16 + 3 * QPC * 16 + MAXK * 4 + GCELLS * 2;
    cudaFuncSetAttribute(flow_kernel, cudaFuncAttributeMaxDynamicSharedMemorySize, smem_main);

    prep_a_kernel<<<NLAYERS, PREPA_T>>>(sW1, sb1, sW2, sb2, tW1, tb1, tW2, tb2);
    prep_b_kernel<<<NLAYERS * SPLIT, PREPB_T>>>(sW1, sb1, sW2, sb2, sW3, sb3,
                                                tW1, tb1, tW2, tb2, tW3, tb3);
    flow_kernel<<<grid, MAIN_T, smem_main>>>(x, scale_w, scale_b, out, nquads);
}

// round 17
// speedup vs baseline: 2.0266x; 1.0686x over previous
#include <cuda_runtime.h>
#include <cstdint>
#include <math_constants.h>

// RealNVP, exact piecewise-linear collapse.
// R17 over R16 (247.9us = ~14.8 prep_a + ~8 prep_b + ~225 flow):
//  (1) fast_tanh uses rcp.approx.f32 (1 MUFU) instead of __frcp_rn's
//      correctly-rounded Newton sequence: ~7 fewer dependent instrs per eval.
//  (2) prep_a: O(m^2) parallel rank-sort of the merged knots replaces the
//      55-stage barrier-bound bitonic (prep_a 14.8 -> ~5us).

#define NLAYERS 15
#define MAXK    1280          // merged knees bound: 2*560=1120
#define GCELLS  8192
#define PREPA_T 512
#define PREPB_T 256
#define SPLIT   8             // prep_b blocks per layer
#define MAIN_T  1024
#define QPC     3543          // quads per CTA; 296 CTAs for N=4194304

__device__ float  g_B [NLAYERS][MAXK];      // knots; B[0]=-inf, +inf padded
__device__ float4 g_AV[NLAYERS][MAXK];      // (Ss, Cs, St, Ct) intercept form
__device__ unsigned short g_grid[NLAYERS][GCELLS];  // bit15=impure, low15=idx
__device__ float  g_x0[NLAYERS], g_invh[NLAYERS], g_h[NLAYERS];
__device__ int    g_m[NLAYERS];

__device__ __forceinline__ float fast_tanh(float x) {
    float e = __expf(2.0f * x);
    float r;
    asm("rcp.approx.f32 %0, %1;" : "=f"(r) : "f"(e + 1.0f));
    return fmaf(-2.0f, r, 1.0f);
}

// ---------------------------------------------------------------------------
// prep_a: one block per layer. Knees -> parallel rank-sort -> B, m, grid params.
// ---------------------------------------------------------------------------
__global__ __launch_bounds__(PREPA_T, 1) void prep_a_kernel(
    const float* __restrict__ sW1, const float* __restrict__ sb1,
    const float* __restrict__ sW2, const float* __restrict__ sb2,
    const float* __restrict__ tW1, const float* __restrict__ tb1,
    const float* __restrict__ tW2, const float* __restrict__ tb2)
{
    __shared__ float w1[2][32], b1[2][32], W2s[2][512], b2s[2][16];
    __shared__ float K[MAXK];
    __shared__ float S[MAXK];
    __shared__ float X[34];
    __shared__ float tmpX[32];
    __shared__ int   vflag[32];
    __shared__ int cnt, m1s;

    int tid = threadIdx.x;
    int l = blockIdx.x;

    for (int i = tid; i < 32; i += PREPA_T) {
        w1[0][i] = sW1[l*32+i]; b1[0][i] = sb1[l*32+i];
        w1[1][i] = tW1[l*32+i]; b1[1][i] = tb1[l*32+i];
    }
    for (int i = tid; i < 512; i += PREPA_T) {
        W2s[0][i] = sW2[l*512+i]; W2s[1][i] = tW2[l*512+i];
    }
    for (int i = tid; i < 16; i += PREPA_T) {
        b2s[0][i] = sb2[l*16+i]; b2s[1][i] = tb2[l*16+i];
    }
    if (tid == 0) cnt = 0;
    __syncthreads();

    for (int p = 0; p < 2; p++) {
        int c0 = cnt;                      // uniform (post-sync)
        // parallel rank-sort of the <=32 L1 knees
        if (tid < 32) {
            float w = w1[p][tid], b = b1[p][tid];
            bool valid = (w != 0.0f);
            tmpX[tid] = valid ? (-b / w) : 0.0f;
            vflag[tid] = valid ? 1 : 0;
        }
        __syncthreads();
        if (tid < 32 && vflag[tid]) {
            float xi = tmpX[tid];
            int rank = 0;
            for (int j = 0; j < 32; j++) {
                if (vflag[j]) {
                    float xj = tmpX[j];
                    if (xj < xi || (xj == xi && j < tid)) rank++;
                }
            }
            X[rank + 1] = xi;
        }
        if (tid == 0) {
            int m1 = 0;
            for (int j = 0; j < 32; j++) m1 += vflag[j];
            m1s = m1;
            X[0] = -CUDART_INF_F;
        }
        __syncthreads();
        int m1 = m1s;
        if (tid == 0) {
            X[m1 + 1] = CUDART_INF_F;
            cnt = c0 + m1;
        }
        if (tid < 32 && tid < m1) K[c0 + tid] = X[tid + 1];
        __syncthreads();

        // layer-2 knees: a2_j linear within each L1 interval -> <=1 root each
        int ntask = (m1 + 1) * 16;
        for (int t = tid; t < ntask; t += PREPA_T) {
            int iv = t >> 4, j = t & 15;
            float lo = X[iv], hi = X[iv + 1];
            float xm;
            if (!isfinite(lo) && !isfinite(hi)) xm = 0.0f;
            else if (!isfinite(lo)) xm = hi - 1.0f;
            else if (!isfinite(hi)) xm = lo + 1.0f;
            else xm = 0.5f * (lo + hi);
            float c = b2s[p][j], d = 0.0f;
            for (int i = 0; i < 32; i++) {
                float pre = fmaf(w1[p][i], xm, b1[p][i]);
                float s1 = (pre >= 0.0f) ? 1.0f : 0.01f;
                float wij = W2s[p][i * 16 + j];
                d = fmaf(wij * s1, w1[p][i], d);
                c = fmaf(wij * s1, b1[p][i], c);
            }
            if (d != 0.0f) {
                float r = -c / d;
                if (isfinite(r) && r > lo && r < hi) {
                    int pos = atomicAdd(&cnt, 1);
                    if (pos < MAXK - 2) K[pos] = r;
                }
            }
        }
        __syncthreads();
    }
    int m = cnt;
    if (m > MAXK - 2) m = MAXK - 2;        // paranoia clamp (bound is 1120)

    // O(m^2) parallel rank-sort: each thread ranks its knot(s); 2 barriers.
    for (int k = tid; k < m; k += PREPA_T) {
        float v = K[k];
        int rank = 0;
        for (int j = 0; j < m; j++) {
            float u = K[j];                // broadcast read
            rank += (u < v || (u == v && j < k)) ? 1 : 0;
        }
        S[rank] = v;
    }
    __syncthreads();

    for (int kk = tid; kk < MAXK; kk += PREPA_T) {
        float v = (kk == 0) ? -CUDART_INF_F : (kk <= m ? S[kk - 1] : CUDART_INF_F);
        g_B[l][kk] = v;
    }
    if (tid == 0) {
        g_m[l] = m;
        float x0 = (m >= 1) ? S[0] : 0.0f;
        float xr = (m >= 1) ? S[m - 1] : 0.0f;
        float invh = (m >= 2 && xr > x0) ? (float)GCELLS / (xr - x0) : 0.0f;
        g_x0[l] = x0;
        g_invh[l] = invh;
        g_h[l] = (invh > 0.0f) ? (xr - x0) / (float)GCELLS : 0.0f;
    }
}

// ---------------------------------------------------------------------------
// prep_b: SPLIT blocks per layer. Per-segment intercept payloads + grid cells.
// ---------------------------------------------------------------------------
__global__ __launch_bounds__(PREPB_T, 1) void prep_b_kernel(
    const float* __restrict__ sW1, const float* __restrict__ sb1,
    const float* __restrict__ sW2, const float* __restrict__ sb2,
    const float* __restrict__ sW3, const float* __restrict__ sb3,
    const float* __restrict__ tW1, const float* __restrict__ tb1,
    const float* __restrict__ tW2, const float* __restrict__ tb2,
    const float* __restrict__ tW3, const float* __restrict__ tb3)
{
    __shared__ float w1[2][32], b1[2][32], W2s[2][512], b2s[2][16], w3s[2][16], b3s[2];

    int tid = threadIdx.x;
    int l = blockIdx.x / SPLIT;
    int s = blockIdx.x % SPLIT;

    for (int i = tid; i < 32; i += PREPB_T) {
        w1[0][i] = sW1[l*32+i]; b1[0][i] = sb1[l*32+i];
        w1[1][i] = tW1[l*32+i]; b1[1][i] = tb1[l*32+i];
    }
    for (int i = tid; i < 512; i += PREPB_T) {
        W2s[0][i] = sW2[l*512+i]; W2s[1][i] = tW2[l*512+i];
    }
    for (int i = tid; i < 16; i += PREPB_T) {
        b2s[0][i] = sb2[l*16+i]; w3s[0][i] = sW3[l*16+i];
        b2s[1][i] = tb2[l*16+i]; w3s[1][i] = tW3[l*16+i];
    }
    if (tid == 0) { b3s[0] = sb3[l]; b3s[1] = tb3[l]; }
    __syncthreads();

    int m = g_m[l];
    const float* B = g_B[l];

    const int CH = MAXK / SPLIT;                  // 160
    for (int idx = s * CH + tid; idx < (s + 1) * CH; idx += PREPB_T) {
        if (idx > m) {
            g_AV[l][idx] = make_float4(0.f, 0.f, 0.f, 0.f);
            continue;
        }
        float Bl = B[idx];
        float Br = B[idx + 1];
        float A  = isfinite(Bl) ? Bl : ((m >= 1) ? B[1] : 0.0f);
        float xm;
        if (!isfinite(Bl) && !isfinite(Br)) xm = 0.0f;
        else if (!isfinite(Bl)) xm = Br - 1.0f;
        else if (!isfinite(Br)) xm = Bl + 1.0f;
        else { xm = 0.5f * (Bl + Br); if (!(xm > Bl && xm < Br)) xm = Bl; }

        float V[2], S[2];
        for (int p = 0; p < 2; p++) {
            float acc[16];
#pragma unroll
            for (int j = 0; j < 16; j++) acc[j] = b2s[p][j];
            for (int i = 0; i < 32; i++) {
                float pre = fmaf(w1[p][i], A, b1[p][i]);
                float h = fmaxf(pre, 0.01f * pre);
#pragma unroll
                for (int j = 0; j < 16; j++) acc[j] = fmaf(h, W2s[p][i * 16 + j], acc[j]);
            }
            float Vv = b3s[p];
#pragma unroll
            for (int j = 0; j < 16; j++) {
                float hh = fmaxf(acc[j], 0.01f * acc[j]);
                Vv = fmaf(hh, w3s[p][j], Vv);
            }
            float a2[16], dd[16];
#pragma unroll
            for (int j = 0; j < 16; j++) { a2[j] = b2s[p][j]; dd[j] = 0.0f; }
            for (int i = 0; i < 32; i++) {
                float pre = fmaf(w1[p][i], xm, b1[p][i]);
                float s1 = (pre >= 0.0f) ? 1.0f : 0.01f;
                float h = s1 * pre;
                float dh = s1 * w1[p][i];
#pragma unroll
                for (int j = 0; j < 16; j++) {
                    float wij = W2s[p][i * 16 + j];
                    a2[j] = fmaf(h, wij, a2[j]);
                    dd[j] = fmaf(dh, wij, dd[j]);
                }
            }
            float Sv = 0.0f;
#pragma unroll
            for (int j = 0; j < 16; j++) {
                float s2 = (a2[j] >= 0.0f) ? 1.0f : 0.01f;
                Sv = fmaf(w3s[p][j] * s2, dd[j], Sv);
            }
            V[p] = Vv; S[p] = Sv;
        }
        // intercept form: C = V - S*A ; eval is fma(S, x, C)
        float Cs = fmaf(-S[0], A, V[0]);
        float Ct = fmaf(-S[1], A, V[1]);
        g_AV[l][idx] = make_float4(S[0], Cs, S[1], Ct);
    }

    const int GC = GCELLS / SPLIT;                // 1024
    float x0 = g_x0[l], h = g_h[l];
    float wd = 0.01f * h;
    for (int g = s * GC + tid; g < (s + 1) * GC; g += PREPB_T) {
        int ilo = 0, ihi = 0;
        if (m >= 1) {
            float xlo = x0 + (float)g * h - wd;
            float xhi = x0 + (float)(g + 1) * h + wd;
            int lo = 0, hi = m;
            while (lo < hi) { int mid = (lo + hi + 1) >> 1; if (B[mid] <= xlo) lo = mid; else hi = mid - 1; }
            ilo = lo;
            lo = 0; hi = m;
            while (lo < hi) { int mid = (lo + hi + 1) >> 1; if (B[mid] <= xhi) lo = mid; else hi = mid - 1; }
            ihi = lo;
        }
        bool impure = (ilo != ihi) || (g == 0) || (g == GCELLS - 1);
        g_grid[l][g] = (unsigned short)(ilo | (impure ? 0x8000 : 0));
    }
}

// ---------------------------------------------------------------------------
// Flow kernel: smem ping-pong state + pure-cell fast path + intercept eval.
// ---------------------------------------------------------------------------
extern __shared__ float4 smb[];

__global__ __launch_bounds__(MAIN_T, 1) void flow_kernel(
    const float* __restrict__ x,
    const float* __restrict__ scale_w, const float* __restrict__ scale_b,
    float* __restrict__ out, int nquads)
{
    float4* AVs = smb;                     // MAXK float4
    float4* SZa = AVs + MAXK;              // QPC  (ping)
    float4* SZb = SZa + QPC;               // QPC  (pong)
    float4* SLD = SZb + QPC;               // QPC
    float*  Bs  = (float*)(SLD + QPC);     // MAXK
    unsigned short* Gs = (unsigned short*)(Bs + MAXK);  // GCELLS

    int tid = threadIdx.x;
    int q0 = blockIdx.x * QPC;
    int nq = nquads - q0;
    if (nq > QPC) nq = QPC;

    // P holds z2 (x1 source), Q holds z1 (x2 source)
    float4* P = SZa;
    float4* Q = SZb;

    const float4* x4 = (const float4*)x;
    for (int lq = tid; lq < nq; lq += MAIN_T) {
        int Qi = q0 + lq;
        float4 a = x4[2 * Qi], b = x4[2 * Qi + 1];
        Q[lq] = make_float4(a.y, a.w, b.y, b.w);   // z1 = x[:,1]
        P[lq] = make_float4(a.x, a.z, b.x, b.z);   // z2 = x[:,0]
        SLD[lq] = make_float4(0.f, 0.f, 0.f, 0.f);
    }

    for (int l = 0; l < NLAYERS; l++) {
        __syncthreads();
        {
            const float*  gB = g_B[l];
            const float4* gA = g_AV[l];
            const unsigned short* gG = g_grid[l];
            for (int k = tid; k < MAXK; k += MAIN_T) {
                Bs[k] = gB[k]; AVs[k] = gA[k];
            }
            for (int g = tid; g < GCELLS; g += MAIN_T) Gs[g] = gG[g];
        }
        int mloc = g_m[l];
        float x0 = g_x0[l], invh = g_invh[l];
        float sw = scale_w[l], sb = scale_b[l];
        __syncthreads();

        for (int lq = tid; lq < nq; lq += MAIN_T) {
            float4 z2 = P[lq], z1 = Q[lq], ld = SLD[lq];
            float x1v[4] = {z2.x, z2.y, z2.z, z2.w};
            float x2v[4] = {z1.x, z1.y, z1.z, z1.w};
            float zn[4], lg[4];
#pragma unroll
            for (int e = 0; e < 4; e++) {
                float xv = x1v[e];
                int c = (int)((xv - x0) * invh);
                c = min(max(c, 0), GCELLS - 1);
                unsigned int e16 = Gs[c];
                int idx = e16 & 0x7FFF;
                if (e16 & 0x8000u) {
                    while (idx < mloc && Bs[idx + 1] <= xv) idx++;
                }
                float4 av = AVs[idx];
                float sv = fmaf(av.x, xv, av.y);
                float tv = fmaf(av.z, xv, av.w);
                float logs = fmaf(fast_tanh(sv), sw, sb);
                zn[e] = fmaf(__expf(logs), x2v[e], tv);
                lg[e] = logs;
            }
            Q[lq] = make_float4(zn[0], zn[1], zn[2], zn[3]);  // new z2
            SLD[lq] = make_float4(ld.x + lg[0], ld.y + lg[1],
                                  ld.z + lg[2], ld.w + lg[3]);
        }
        // swap roles: new z1 = old z2 (P), new z2 in Q
        float4* tmp = P; P = Q; Q = tmp;
    }
    __syncthreads();

    float4* o4  = (float4*)out;
    float4* ld4 = (float4*)(out + 8 * (size_t)nquads);
    for (int lq = tid; lq < nq; lq += MAIN_T) {
        int Qi = q0 + lq;
        float4 z2 = P[lq], z1 = Q[lq];     // P=z2_final, Q=z1_final
        o4[2 * Qi]     = make_float4(z1.x, z2.x, z1.y, z2.y);
        o4[2 * Qi + 1] = make_float4(z1.z, z2.z, z1.w, z2.w);
        ld4[Qi] = SLD[lq];
    }
}

extern "C" void kernel_launch(void* const* d_in, const int* in_sizes, int n_in,
                              void* d_out, int out_size) {
    const float* x       = (const float*)d_in[0];
    const float* scale_w = (const float*)d_in[1];
    const float* scale_b = (const float*)d_in[2];
    const float* sW1 = (const float*)d_in[3];
    const float* sb1 = (const float*)d_in[4];
    const float* sW2 = (const float*)d_in[5];
    const float* sb2 = (const float*)d_in[6];
    const float* sW3 = (const float*)d_in[7];
    const float* sb3 = (const float*)d_in[8];
    const float* tW1 = (const float*)d_in[9];
    const float* tb1 = (const float*)d_in[10];
    const float* tW2 = (const float*)d_in[11];
    const float* tb2 = (const float*)d_in[12];
    const float* tW3 = (const float*)d_in[13];
    const float* tb3 = (const float*)d_in[14];
    float* out = (float*)d_out;

    int nquads = in_sizes[0] / 8;
    int grid = (nquads + QPC - 1) / QPC;   // 296 for N=4194304

    // smem: AV float4 + 3*QPC float4 + Bs float + grid u16 = 212,048 B
    const int smem_main = MAXK * 16 + 3 * QPC * 16 + MAXK * 4 + GCELLS * 2;
    cudaFuncSetAttribute(flow_kernel, cudaFuncAttributeMaxDynamicSharedMemorySize, smem_main);

    prep_a_kernel<<<NLAYERS, PREPA_T>>>(sW1, sb1, sW2, sb2, tW1, tb1, tW2, tb2);
    prep_b_kernel<<<NLAYERS * SPLIT, PREPB_T>>>(sW1, sb1, sW2, sb2, sW3, sb3,
                                                tW1, tb1, tW2, tb2, tW3, tb3);
    flow_kernel<<<grid, MAIN_T, smem_main>>>(x, scale_w, scale_b, out, nquads);
}